// round 5
// baseline (speedup 1.0000x reference)
#include <cuda_runtime.h>

// Net_2095944040841: 3-layer LSTM (reference's buggy c-state wiring) on GB300.
// R5 = R3 base + (a) cell3 reduced to 150 live gate rows (f-gate dead since c3==0),
// rebalanced across warps via slot map; (b) HW tanh.approx activations, branchless.

#define T_LEN 1024
#define IN_D  20
#define HIDN  50
#define OUT_D 8
#define NB    4
#define NCTA  128
#define NTH   160

// shared memory layout (float offsets)
#define WA_STR 76          // cell1 row: 20 fused-x cols + 50 Whh1 cols + 6 pad
#define WA_OFF 0           // 200 x 76
#define WB_OFF 15200       // 200 x 100  [Wih2 | Whh2]
#define WC_OFF 35200       // 200 x 100  [Wih3 | Whh3]
#define BA_OFF 55200       // 200 fused bias cell1
#define BB_OFF 55400
#define BC_OFF 55600
#define W2_OFF 55800       // 8 x 50
#define B2_OFF 56200       // 8
// pair-interleaved inputs: float[pair][batch][2]  (8 floats = 32B per pair)
#define IN1_OFF 56208      // 38 pairs: p0-9 = x(20 cols), p10-34 = h1, p35-37 = pad
#define ST_OFF  56512      // 75 pairs: h1 p0-24 (+0), h2 p25-49 (+200), h3 p50-74 (+400)
#define ACT_OFF 57112      // 200 quads [row][batch] of activated gates
#define SMEM_FLT 57912     // 231,648 bytes

typedef unsigned long long ull;

static __device__ __forceinline__ void upk(ull v, float &a, float &b) {
    asm("mov.b64 {%0,%1}, %2;" : "=f"(a), "=f"(b) : "l"(v));
}
static __device__ __forceinline__ ull fma2(ull a, ull b, ull c) {
    ull d; asm("fma.rn.f32x2 %0, %1, %2, %3;" : "=l"(d) : "l"(a), "l"(b), "l"(c)); return d;
}
static __device__ __forceinline__ float tanhap(float x) {
    float t; asm("tanh.approx.f32 %0, %1;" : "=f"(t) : "f"(x)); return t;
}
static __device__ __forceinline__ float sigm(float x) {
    return fmaf(tanhap(0.5f * x), 0.5f, 0.5f);
}

// Two gate rows (r0, r1) for 4 batches. Row0 activation: sigmoid (always).
// Row1 activation: a1*tanh(k1*x)+c1 (per-thread constants: tanh or sigmoid).
template<int NQ>
static __device__ __forceinline__ void cell_mv2(
    const float* __restrict__ w0row, const float* __restrict__ w1row,
    float bias0, float bias1, float k1, float a1, float c1,
    const float* __restrict__ in, float* __restrict__ actq,
    int r0, int r1)
{
    const ulonglong2* w0q = reinterpret_cast<const ulonglong2*>(w0row);
    const ulonglong2* w1q = reinterpret_cast<const ulonglong2*>(w1row);
    const ulonglong2* q   = reinterpret_cast<const ulonglong2*>(in);
    ull a00 = 0ull, a01 = 0ull, a02 = 0ull, a03 = 0ull;   // row0, batches 0..3
    ull a10 = 0ull, a11 = 0ull, a12 = 0ull, a13 = 0ull;   // row1, batches 0..3
#pragma unroll
    for (int kk = 0; kk < NQ; kk++) {
        ulonglong2 w0 = w0q[kk], w1 = w1q[kk];            // 2 col-pairs per row
        ulonglong2 q0 = q[4*kk+0], q1 = q[4*kk+1];        // pair0: b01, b23
        ulonglong2 q2 = q[4*kk+2], q3 = q[4*kk+3];        // pair1: b01, b23
        a00 = fma2(w0.x, q0.x, a00); a01 = fma2(w0.x, q0.y, a01);
        a02 = fma2(w0.x, q1.x, a02); a03 = fma2(w0.x, q1.y, a03);
        a10 = fma2(w1.x, q0.x, a10); a11 = fma2(w1.x, q0.y, a11);
        a12 = fma2(w1.x, q1.x, a12); a13 = fma2(w1.x, q1.y, a13);
        a00 = fma2(w0.y, q2.x, a00); a01 = fma2(w0.y, q2.y, a01);
        a02 = fma2(w0.y, q3.x, a02); a03 = fma2(w0.y, q3.y, a03);
        a10 = fma2(w1.y, q2.x, a10); a11 = fma2(w1.y, q2.y, a11);
        a12 = fma2(w1.y, q3.x, a12); a13 = fma2(w1.y, q3.y, a13);
    }
    float g0[4], g1[4];
    { float lo, hi;
      upk(a00, lo, hi); g0[0] = lo + hi + bias0;
      upk(a01, lo, hi); g0[1] = lo + hi + bias0;
      upk(a02, lo, hi); g0[2] = lo + hi + bias0;
      upk(a03, lo, hi); g0[3] = lo + hi + bias0;
      upk(a10, lo, hi); g1[0] = lo + hi + bias1;
      upk(a11, lo, hi); g1[1] = lo + hi + bias1;
      upk(a12, lo, hi); g1[2] = lo + hi + bias1;
      upk(a13, lo, hi); g1[3] = lo + hi + bias1; }
    g0[0] = sigm(g0[0]); g0[1] = sigm(g0[1]); g0[2] = sigm(g0[2]); g0[3] = sigm(g0[3]);
    g1[0] = fmaf(tanhap(k1 * g1[0]), a1, c1);
    g1[1] = fmaf(tanhap(k1 * g1[1]), a1, c1);
    g1[2] = fmaf(tanhap(k1 * g1[2]), a1, c1);
    g1[3] = fmaf(tanhap(k1 * g1[3]), a1, c1);
    reinterpret_cast<float4*>(actq)[r0] = make_float4(g0[0], g0[1], g0[2], g0[3]);
    reinterpret_cast<float4*>(actq)[r1] = make_float4(g1[0], g1[1], g1[2], g1[3]);
}

extern __shared__ float sm[];

__global__ void __launch_bounds__(NTH, 1)
lstm_persist_kernel(const float* __restrict__ x,
                    const float* __restrict__ W1,   const float* __restrict__ b1,
                    const float* __restrict__ Wih1, const float* __restrict__ Whh1,
                    const float* __restrict__ bih1, const float* __restrict__ bhh1,
                    const float* __restrict__ Wih2, const float* __restrict__ Whh2,
                    const float* __restrict__ bih2, const float* __restrict__ bhh2,
                    const float* __restrict__ Wih3, const float* __restrict__ Whh3,
                    const float* __restrict__ bih3, const float* __restrict__ bhh3,
                    const float* __restrict__ W2,   const float* __restrict__ b2,
                    float* __restrict__ out)
{
    const int tid = threadIdx.x;
    const int b0  = blockIdx.x * NB;

    // ---------------- init: build fused weights in SMEM ----------------
    for (int i = tid; i < HIDN * IN_D; i += NTH) sm[ST_OFF + i] = W1[i];  // stage W1
    __syncthreads();

    // WA x-part: Wc[r][k] = sum_j Wih1[r][j] * W1[j][k]
    for (int i = tid; i < 200 * IN_D; i += NTH) {
        int r = i / IN_D, k = i % IN_D;
        float acc = 0.f;
#pragma unroll 10
        for (int j = 0; j < HIDN; j++)
            acc += Wih1[r * HIDN + j] * sm[ST_OFF + j * IN_D + k];
        sm[WA_OFF + r * WA_STR + k] = acc;
    }
    for (int i = tid; i < 200 * 56; i += NTH) {
        int r = i / 56, c = i % 56;
        sm[WA_OFF + r * WA_STR + IN_D + c] = (c < HIDN) ? Whh1[r * HIDN + c] : 0.f;
    }
    for (int r = tid; r < 200; r += NTH) {
        float acc = bih1[r] + bhh1[r];
#pragma unroll 10
        for (int j = 0; j < HIDN; j++) acc += Wih1[r * HIDN + j] * b1[j];
        sm[BA_OFF + r] = acc;
        sm[BB_OFF + r] = bih2[r] + bhh2[r];
        sm[BC_OFF + r] = bih3[r] + bhh3[r];
    }
    for (int i = tid; i < 200 * 100; i += NTH) {
        int r = i / 100, c = i % 100;
        sm[WB_OFF + i] = (c < HIDN) ? Wih2[r * HIDN + c] : Whh2[r * HIDN + c - HIDN];
        sm[WC_OFF + i] = (c < HIDN) ? Wih3[r * HIDN + c] : Whh3[r * HIDN + c - HIDN];
    }
    for (int i = tid; i < OUT_D * HIDN; i += NTH) sm[W2_OFF + i] = W2[i];
    if (tid < OUT_D) sm[B2_OFF + tid] = b2[tid];
    __syncthreads();   // W1 staging reads complete

    // zero dynamic regions
    for (int i = tid; i < 304; i += NTH) sm[IN1_OFF + i] = 0.f;
    for (int i = tid; i < 600; i += NTH) sm[ST_OFF + i]  = 0.f;
    for (int i = tid; i < 800; i += NTH) sm[ACT_OFF + i] = 0.f;
    __syncthreads();
    // x(0) into IN1 pair layout: elem (b,k) -> (k>>1)*8 + 2b + (k&1)
    if (tid < NB * IN_D) {
        int b = tid / IN_D, k = tid % IN_D;
        sm[IN1_OFF + (k >> 1) * 8 + 2 * b + (k & 1)] =
            x[((size_t)(b0 + b) * T_LEN) * IN_D + k];
    }
    __syncthreads();

    // ---------------- role setup ----------------
    const int lane = tid & 31, wrp = tid >> 5;
    const bool isgate = (wrp < 4) && (lane < 25);
    const int g = wrp * 25 + lane;              // rows g, g+100 for cells 1,2
    const bool ishelp = (wrp == 4);
    const int u7 = tid - 128;
    const int e0 = u7, e1 = u7 + 32, e2 = u7 + 64;
    const int ob = u7 >> 3, oo = u7 & 7;

    // cells 1,2 row1 activation params: g-gate (tanh) if g<50 else o-gate (sigmoid)
    const float k12 = (g < 50) ? 1.0f : 0.5f;
    const float a12 = (g < 50) ? 1.0f : 0.5f;
    const float c12 = (g < 50) ? 0.0f : 0.5f;

    // cell3 slot map: 150 live rows (i 0-49, g 100-149, o 150-199) in 75 slots,
    // slot s -> thread (s%4)*25 + s/4. Inverse: s = 4*lane + wrp, active if s<75.
    const int s3 = 4 * lane + wrp;
    const bool is3 = isgate && (s3 < 75);
    const int r3a = (s3 < 50) ? s3 : 150 + 2 * (s3 - 50);          // i or o (sigmoid)
    const int r3b = (s3 < 50) ? s3 + 100 : 151 + 2 * (s3 - 50);    // g or o
    const float k3 = (r3b < 150) ? 1.0f : 0.5f;
    const float a3 = (r3b < 150) ? 1.0f : 0.5f;
    const float c3 = (r3b < 150) ? 0.0f : 0.5f;

    const float* wa0 = sm + WA_OFF + g * WA_STR;
    const float* wa1 = sm + WA_OFF + (g + 100) * WA_STR;
    const float* wb0 = sm + WB_OFF + g * 100;
    const float* wb1 = sm + WB_OFF + (g + 100) * 100;
    const float* wc0 = sm + WC_OFF + r3a * 100;
    const float* wc1 = sm + WC_OFF + r3b * 100;
    const float ba0 = isgate ? sm[BA_OFF + g] : 0.f;
    const float ba1 = isgate ? sm[BA_OFF + g + 100] : 0.f;
    const float bb0 = isgate ? sm[BB_OFF + g] : 0.f;
    const float bb1 = isgate ? sm[BB_OFF + g + 100] : 0.f;
    const float bc0 = is3 ? sm[BC_OFF + r3a] : 0.f;
    const float bc1 = is3 ? sm[BC_OFF + r3b] : 0.f;

    float c1s[NB] = {0.f, 0.f, 0.f, 0.f};
    float czs[NB] = {0.f, 0.f, 0.f, 0.f};
    const int up = tid >> 1, us = tid & 1;

    for (int t = 0; t < T_LEN; t++) {
        float xv0 = 0.f, xv1 = 0.f, xv2 = 0.f;
        const bool xl = (t + 1 < T_LEN);

        // ---- phase 1: gate1 || helper {x(t+1) prefetch, out(t-1)} ----
        if (isgate) {
            cell_mv2<19>(wa0, wa1, ba0, ba1, k12, a12, c12,
                         sm + IN1_OFF, sm + ACT_OFF, g, g + 100);
        } else if (ishelp) {
            if (xl) {
                { int b = e0 / IN_D, k = e0 % IN_D;
                  xv0 = x[((size_t)(b0 + b) * T_LEN + (t + 1)) * IN_D + k]; }
                { int b = e1 / IN_D, k = e1 % IN_D;
                  xv1 = x[((size_t)(b0 + b) * T_LEN + (t + 1)) * IN_D + k]; }
                if (e2 < NB * IN_D) {
                  int b = e2 / IN_D, k = e2 % IN_D;
                  xv2 = x[((size_t)(b0 + b) * T_LEN + (t + 1)) * IN_D + k]; }
            }
            if (t > 0) {   // out-projection for step t-1 (h3 pairs at ST+400)
                float acc = sm[B2_OFF + oo];
#pragma unroll
                for (int j = 0; j < HIDN; j++)
                    acc += sm[W2_OFF + oo * HIDN + j] *
                           sm[ST_OFF + 400 + (j >> 1) * 8 + 2 * ob + (j & 1)];
                out[((size_t)(b0 + ob) * T_LEN + (t - 1)) * OUT_D + oo] = acc;
            }
        }
        __syncthreads();

        // ---- phase 2: upd1 || helper stores x(t+1) ----
        if (tid < HIDN) {
            float4 iq = reinterpret_cast<float4*>(sm + ACT_OFF)[tid];
            float4 fq = reinterpret_cast<float4*>(sm + ACT_OFF)[50 + tid];
            float4 gq = reinterpret_cast<float4*>(sm + ACT_OFF)[100 + tid];
            float4 oq = reinterpret_cast<float4*>(sm + ACT_OFF)[150 + tid];
            float h[NB];
            c1s[0] = fq.x * c1s[0] + iq.x * gq.x;  h[0] = oq.x * tanhap(c1s[0]);
            c1s[1] = fq.y * c1s[1] + iq.y * gq.y;  h[1] = oq.y * tanhap(c1s[1]);
            c1s[2] = fq.z * c1s[2] + iq.z * gq.z;  h[2] = oq.z * tanhap(c1s[2]);
            c1s[3] = fq.w * c1s[3] + iq.w * gq.w;  h[3] = oq.w * tanhap(c1s[3]);
#pragma unroll
            for (int b = 0; b < NB; b++) {
                sm[ST_OFF  + up * 8 + 2 * b + us]        = h[b];
                sm[IN1_OFF + (10 + up) * 8 + 2 * b + us] = h[b];
            }
        } else if (ishelp && xl) {
            { int b = e0 / IN_D, k = e0 % IN_D;
              sm[IN1_OFF + (k >> 1) * 8 + 2 * b + (k & 1)] = xv0; }
            { int b = e1 / IN_D, k = e1 % IN_D;
              sm[IN1_OFF + (k >> 1) * 8 + 2 * b + (k & 1)] = xv1; }
            if (e2 < NB * IN_D) {
              int b = e2 / IN_D, k = e2 % IN_D;
              sm[IN1_OFF + (k >> 1) * 8 + 2 * b + (k & 1)] = xv2; }
        }
        __syncthreads();

        // ---- phase 3: gate2 from [h1 | h2] pairs ----
        if (isgate)
            cell_mv2<25>(wb0, wb1, bb0, bb1, k12, a12, c12,
                         sm + ST_OFF, sm + ACT_OFF, g, g + 100);
        __syncthreads();

        // ---- phase 4: upd2 (state = cz from prev step's cell3) ----
        if (tid < HIDN) {
            float4 iq = reinterpret_cast<float4*>(sm + ACT_OFF)[tid];
            float4 fq = reinterpret_cast<float4*>(sm + ACT_OFF)[50 + tid];
            float4 gq = reinterpret_cast<float4*>(sm + ACT_OFF)[100 + tid];
            float4 oq = reinterpret_cast<float4*>(sm + ACT_OFF)[150 + tid];
            float c2t, h[NB];
            c2t = fq.x * czs[0] + iq.x * gq.x;  h[0] = oq.x * tanhap(c2t);
            c2t = fq.y * czs[1] + iq.y * gq.y;  h[1] = oq.y * tanhap(c2t);
            c2t = fq.z * czs[2] + iq.z * gq.z;  h[2] = oq.z * tanhap(c2t);
            c2t = fq.w * czs[3] + iq.w * gq.w;  h[3] = oq.w * tanhap(c2t);
#pragma unroll
            for (int b = 0; b < NB; b++)
                sm[ST_OFF + 200 + up * 8 + 2 * b + us] = h[b];   // h2 pairs
        }
        __syncthreads();

        // ---- phase 5: gate3 from [h2 | h3]; only 150 live rows (f-gate dead) ----
        if (is3)
            cell_mv2<25>(wc0, wc1, bc0, bc1, k3, a3, c3,
                         sm + ST_OFF + 200, sm + ACT_OFF, r3a, r3b);
        __syncthreads();

        // ---- phase 6: upd3 (c_new = i*g; cz <- c_new) ----
        if (tid < HIDN) {
            float4 iq = reinterpret_cast<float4*>(sm + ACT_OFF)[tid];
            float4 gq = reinterpret_cast<float4*>(sm + ACT_OFF)[100 + tid];
            float4 oq = reinterpret_cast<float4*>(sm + ACT_OFF)[150 + tid];
            float h[NB];
            czs[0] = iq.x * gq.x;  h[0] = oq.x * tanhap(czs[0]);
            czs[1] = iq.y * gq.y;  h[1] = oq.y * tanhap(czs[1]);
            czs[2] = iq.z * gq.z;  h[2] = oq.z * tanhap(czs[2]);
            czs[3] = iq.w * gq.w;  h[3] = oq.w * tanhap(czs[3]);
#pragma unroll
            for (int b = 0; b < NB; b++)
                sm[ST_OFF + 400 + up * 8 + 2 * b + us] = h[b];   // h3 pairs
        }
        __syncthreads();
    }

    // tail: out-projection for the final step
    if (ishelp) {
        float acc = sm[B2_OFF + oo];
#pragma unroll
        for (int j = 0; j < HIDN; j++)
            acc += sm[W2_OFF + oo * HIDN + j] *
                   sm[ST_OFF + 400 + (j >> 1) * 8 + 2 * ob + (j & 1)];
        out[((size_t)(b0 + ob) * T_LEN + (T_LEN - 1)) * OUT_D + oo] = acc;
    }
}

extern "C" void kernel_launch(void* const* d_in, const int* in_sizes, int n_in,
                              void* d_out, int out_size)
{
    const float* x    = (const float*)d_in[0];
    const float* W1   = (const float*)d_in[1];
    const float* b1   = (const float*)d_in[2];
    const float* Wih1 = (const float*)d_in[3];
    const float* Whh1 = (const float*)d_in[4];
    const float* bih1 = (const float*)d_in[5];
    const float* bhh1 = (const float*)d_in[6];
    const float* Wih2 = (const float*)d_in[7];
    const float* Whh2 = (const float*)d_in[8];
    const float* bih2 = (const float*)d_in[9];
    const float* bhh2 = (const float*)d_in[10];
    const float* Wih3 = (const float*)d_in[11];
    const float* Whh3 = (const float*)d_in[12];
    const float* bih3 = (const float*)d_in[13];
    const float* bhh3 = (const float*)d_in[14];
    const float* W2   = (const float*)d_in[15];
    const float* b2   = (const float*)d_in[16];
    float* out = (float*)d_out;

    const int smem_bytes = SMEM_FLT * sizeof(float);  // 231,648
    cudaFuncSetAttribute(lstm_persist_kernel,
                         cudaFuncAttributeMaxDynamicSharedMemorySize, smem_bytes);

    lstm_persist_kernel<<<NCTA, NTH, smem_bytes>>>(
        x, W1, b1, Wih1, Whh1, bih1, bhh1,
        Wih2, Whh2, bih2, bhh2, Wih3, Whh3, bih3, bhh3,
        W2, b2, out);
}

// round 6
// speedup vs baseline: 1.9470x; 1.9470x over previous
#include <cuda_runtime.h>

// Net_2095944040841: 3-layer LSTM (reference's buggy c-state wiring) on GB300.
// R6 = R3 base + (a) tanh.approx activations, (b) cell3 trimmed to 150 live rows
// with LANE-CONTIGUOUS (conflict-free) mapping, (c) updates distributed over
// 100 gate threads (2 tasks each) instead of 50 threads x 4 batches.

#define T_LEN 1024
#define IN_D  20
#define HIDN  50
#define OUT_D 8
#define NB    4
#define NCTA  128
#define NTH   160

// shared memory layout (float offsets)
#define WA_STR 76          // cell1 row: 20 fused-x cols + 50 Whh1 cols + 6 pad
#define WA_OFF 0           // 200 x 76
#define WB_OFF 15200       // 200 x 100  [Wih2 | Whh2]
#define WC_OFF 35200       // 200 x 100  [Wih3 | Whh3]
#define BA_OFF 55200       // 200 fused bias cell1
#define BB_OFF 55400
#define BC_OFF 55600
#define W2_OFF 55800       // 8 x 50
#define B2_OFF 56200       // 8
// pair-interleaved inputs: float[pair][batch][2]  (8 floats = 32B per pair)
#define IN1_OFF 56208      // 38 pairs: p0-9 = x(20 cols), p10-34 = h1, p35-37 = pad
#define ST_OFF  56512      // 75 pairs: h1 p0-24 (+0), h2 p25-49 (+200), h3 p50-74 (+400)
#define ACT_OFF 57112      // 200 quads [row][batch] of activated gates
#define SMEM_FLT 57912     // 231,648 bytes

typedef unsigned long long ull;

static __device__ __forceinline__ void upk(ull v, float &a, float &b) {
    asm("mov.b64 {%0,%1}, %2;" : "=f"(a), "=f"(b) : "l"(v));
}
static __device__ __forceinline__ ull fma2(ull a, ull b, ull c) {
    ull d; asm("fma.rn.f32x2 %0, %1, %2, %3;" : "=l"(d) : "l"(a), "l"(b), "l"(c)); return d;
}
static __device__ __forceinline__ float tanhap(float x) {
    float t; asm("tanh.approx.f32 %0, %1;" : "=f"(t) : "f"(x)); return t;
}
static __device__ __forceinline__ float sigm(float x) {
    return fmaf(tanhap(0.5f * x), 0.5f, 0.5f);
}

// Two gate rows (r0, r1) for 4 batches. Activation y = a*tanh(k*x)+c per row:
// sigmoid = (0.5, 0.5, 0.5), tanh = (1, 1, 0).
template<int NQ>
static __device__ __forceinline__ void cell_mv2(
    const float* __restrict__ w0row, const float* __restrict__ w1row,
    float bias0, float bias1,
    float k0, float a0, float c0, float k1, float a1, float c1,
    const float* __restrict__ in, float* __restrict__ actq,
    int r0, int r1)
{
    const ulonglong2* w0q = reinterpret_cast<const ulonglong2*>(w0row);
    const ulonglong2* w1q = reinterpret_cast<const ulonglong2*>(w1row);
    const ulonglong2* q   = reinterpret_cast<const ulonglong2*>(in);
    ull a00 = 0ull, a01 = 0ull, a02 = 0ull, a03 = 0ull;   // row0, batches 0..3
    ull a10 = 0ull, a11 = 0ull, a12 = 0ull, a13 = 0ull;   // row1, batches 0..3
#pragma unroll
    for (int kk = 0; kk < NQ; kk++) {
        ulonglong2 w0 = w0q[kk], w1 = w1q[kk];            // 2 col-pairs per row
        ulonglong2 q0 = q[4*kk+0], q1 = q[4*kk+1];        // pair0: b01, b23
        ulonglong2 q2 = q[4*kk+2], q3 = q[4*kk+3];        // pair1: b01, b23
        a00 = fma2(w0.x, q0.x, a00); a01 = fma2(w0.x, q0.y, a01);
        a02 = fma2(w0.x, q1.x, a02); a03 = fma2(w0.x, q1.y, a03);
        a10 = fma2(w1.x, q0.x, a10); a11 = fma2(w1.x, q0.y, a11);
        a12 = fma2(w1.x, q1.x, a12); a13 = fma2(w1.x, q1.y, a13);
        a00 = fma2(w0.y, q2.x, a00); a01 = fma2(w0.y, q2.y, a01);
        a02 = fma2(w0.y, q3.x, a02); a03 = fma2(w0.y, q3.y, a03);
        a10 = fma2(w1.y, q2.x, a10); a11 = fma2(w1.y, q2.y, a11);
        a12 = fma2(w1.y, q3.x, a12); a13 = fma2(w1.y, q3.y, a13);
    }
    float g0[4], g1[4];
    { float lo, hi;
      upk(a00, lo, hi); g0[0] = lo + hi + bias0;
      upk(a01, lo, hi); g0[1] = lo + hi + bias0;
      upk(a02, lo, hi); g0[2] = lo + hi + bias0;
      upk(a03, lo, hi); g0[3] = lo + hi + bias0;
      upk(a10, lo, hi); g1[0] = lo + hi + bias1;
      upk(a11, lo, hi); g1[1] = lo + hi + bias1;
      upk(a12, lo, hi); g1[2] = lo + hi + bias1;
      upk(a13, lo, hi); g1[3] = lo + hi + bias1; }
    g0[0] = fmaf(tanhap(k0 * g0[0]), a0, c0);
    g0[1] = fmaf(tanhap(k0 * g0[1]), a0, c0);
    g0[2] = fmaf(tanhap(k0 * g0[2]), a0, c0);
    g0[3] = fmaf(tanhap(k0 * g0[3]), a0, c0);
    g1[0] = fmaf(tanhap(k1 * g1[0]), a1, c1);
    g1[1] = fmaf(tanhap(k1 * g1[1]), a1, c1);
    g1[2] = fmaf(tanhap(k1 * g1[2]), a1, c1);
    g1[3] = fmaf(tanhap(k1 * g1[3]), a1, c1);
    reinterpret_cast<float4*>(actq)[r0] = make_float4(g0[0], g0[1], g0[2], g0[3]);
    reinterpret_cast<float4*>(actq)[r1] = make_float4(g1[0], g1[1], g1[2], g1[3]);
}

extern __shared__ float sm[];

__global__ void __launch_bounds__(NTH, 1)
lstm_persist_kernel(const float* __restrict__ x,
                    const float* __restrict__ W1,   const float* __restrict__ b1,
                    const float* __restrict__ Wih1, const float* __restrict__ Whh1,
                    const float* __restrict__ bih1, const float* __restrict__ bhh1,
                    const float* __restrict__ Wih2, const float* __restrict__ Whh2,
                    const float* __restrict__ bih2, const float* __restrict__ bhh2,
                    const float* __restrict__ Wih3, const float* __restrict__ Whh3,
                    const float* __restrict__ bih3, const float* __restrict__ bhh3,
                    const float* __restrict__ W2,   const float* __restrict__ b2,
                    float* __restrict__ out)
{
    const int tid = threadIdx.x;
    const int b0  = blockIdx.x * NB;

    // ---------------- init: build fused weights in SMEM ----------------
    for (int i = tid; i < HIDN * IN_D; i += NTH) sm[ST_OFF + i] = W1[i];  // stage W1
    __syncthreads();

    for (int i = tid; i < 200 * IN_D; i += NTH) {
        int r = i / IN_D, k = i % IN_D;
        float acc = 0.f;
#pragma unroll 10
        for (int j = 0; j < HIDN; j++)
            acc += Wih1[r * HIDN + j] * sm[ST_OFF + j * IN_D + k];
        sm[WA_OFF + r * WA_STR + k] = acc;
    }
    for (int i = tid; i < 200 * 56; i += NTH) {
        int r = i / 56, c = i % 56;
        sm[WA_OFF + r * WA_STR + IN_D + c] = (c < HIDN) ? Whh1[r * HIDN + c] : 0.f;
    }
    for (int r = tid; r < 200; r += NTH) {
        float acc = bih1[r] + bhh1[r];
#pragma unroll 10
        for (int j = 0; j < HIDN; j++) acc += Wih1[r * HIDN + j] * b1[j];
        sm[BA_OFF + r] = acc;
        sm[BB_OFF + r] = bih2[r] + bhh2[r];
        sm[BC_OFF + r] = bih3[r] + bhh3[r];
    }
    for (int i = tid; i < 200 * 100; i += NTH) {
        int r = i / 100, c = i % 100;
        sm[WB_OFF + i] = (c < HIDN) ? Wih2[r * HIDN + c] : Whh2[r * HIDN + c - HIDN];
        sm[WC_OFF + i] = (c < HIDN) ? Wih3[r * HIDN + c] : Whh3[r * HIDN + c - HIDN];
    }
    for (int i = tid; i < OUT_D * HIDN; i += NTH) sm[W2_OFF + i] = W2[i];
    if (tid < OUT_D) sm[B2_OFF + tid] = b2[tid];
    __syncthreads();   // W1 staging reads complete

    for (int i = tid; i < 304; i += NTH) sm[IN1_OFF + i] = 0.f;
    for (int i = tid; i < 600; i += NTH) sm[ST_OFF + i]  = 0.f;
    for (int i = tid; i < 800; i += NTH) sm[ACT_OFF + i] = 0.f;
    __syncthreads();
    if (tid < NB * IN_D) {
        int b = tid / IN_D, k = tid % IN_D;
        sm[IN1_OFF + (k >> 1) * 8 + 2 * b + (k & 1)] =
            x[((size_t)(b0 + b) * T_LEN) * IN_D + k];
    }
    __syncthreads();

    // ---------------- role setup ----------------
    const int lane = tid & 31, wrp = tid >> 5;
    const bool isgate = (wrp < 4) && (lane < 25);
    const int g = wrp * 25 + lane;              // rows g, g+100 for cells 1,2
    const bool ishelp = (wrp == 4);
    const int u7 = tid - 128;
    const int e0 = u7, e1 = u7 + 32, e2 = u7 + 64;
    const int ob = u7 >> 3, oo = u7 & 7;

    // cells 1,2 activation params: row0 = sigmoid; row1 = tanh if g<50 else sigmoid
    const float k12 = (g < 50) ? 1.0f : 0.5f;
    const float a12 = k12, c12 = (g < 50) ? 0.0f : 0.5f;

    // cell3 live rows (f-gate rows 50-99 dead since c3==0): 75 slots, slot s owns
    // live rows s and s+75 -> actual rows r3a, r3b. LANE-CONTIGUOUS: s = 19*wrp+lane.
    const int s3 = 19 * wrp + lane;
    const bool is3 = (wrp < 4) && (lane < ((wrp == 3) ? 18 : 19));
    const int r3a = (s3 < 50) ? s3 : s3 + 50;   // i-gate (s<50) or g-gate (100-124)
    const int r3b = s3 + 125;                   // g-gate (125-149) or o-gate (150-199)
    const float k3a = (s3 < 50) ? 0.5f : 1.0f;
    const float a3a = k3a, c3a = (s3 < 50) ? 0.5f : 0.0f;
    const float k3b = (r3b < 150) ? 1.0f : 0.5f;
    const float a3b = k3b, c3b = (r3b < 150) ? 0.0f : 0.5f;

    const float* wa0 = sm + WA_OFF + g * WA_STR;
    const float* wa1 = sm + WA_OFF + (g + 100) * WA_STR;
    const float* wb0 = sm + WB_OFF + g * 100;
    const float* wb1 = sm + WB_OFF + (g + 100) * 100;
    const float* wc0 = sm + WC_OFF + r3a * 100;
    const float* wc1 = sm + WC_OFF + r3b * 100;
    const float ba0 = isgate ? sm[BA_OFF + g] : 0.f;
    const float ba1 = isgate ? sm[BA_OFF + g + 100] : 0.f;
    const float bb0 = isgate ? sm[BB_OFF + g] : 0.f;
    const float bb1 = isgate ? sm[BB_OFF + g + 100] : 0.f;
    const float bc0 = is3 ? sm[BC_OFF + r3a] : 0.f;
    const float bc1 = is3 ? sm[BC_OFF + r3b] : 0.f;

    // distributed updates: gate thread g handles (u, ub) and (u, ub+2)
    const int uu = (g < 50) ? g : g - 50;       // unit 0..49
    const int ubt = (g < 50) ? 0 : 1;           // batch of task A (task B = +2)
    const int up8 = (uu >> 1) * 8 + (uu & 1);   // pair-layout base for unit uu
    float c1s[2] = {0.f, 0.f};                  // cell1 state: tasks A, B
    float czs[2] = {0.f, 0.f};                  // cell3 c_new (acts as c2 next step)

    for (int t = 0; t < T_LEN; t++) {
        float xv0 = 0.f, xv1 = 0.f, xv2 = 0.f;
        const bool xl = (t + 1 < T_LEN);

        // ---- phase 1: gate1 || helper {x(t+1) prefetch, out(t-1)} ----
        if (isgate) {
            cell_mv2<19>(wa0, wa1, ba0, ba1, 0.5f, 0.5f, 0.5f, k12, a12, c12,
                         sm + IN1_OFF, sm + ACT_OFF, g, g + 100);
        } else if (ishelp) {
            if (xl) {
                { int b = e0 / IN_D, k = e0 % IN_D;
                  xv0 = x[((size_t)(b0 + b) * T_LEN + (t + 1)) * IN_D + k]; }
                { int b = e1 / IN_D, k = e1 % IN_D;
                  xv1 = x[((size_t)(b0 + b) * T_LEN + (t + 1)) * IN_D + k]; }
                if (e2 < NB * IN_D) {
                  int b = e2 / IN_D, k = e2 % IN_D;
                  xv2 = x[((size_t)(b0 + b) * T_LEN + (t + 1)) * IN_D + k]; }
            }
            if (t > 0) {
                float acc = sm[B2_OFF + oo];
#pragma unroll
                for (int j = 0; j < HIDN; j++)
                    acc += sm[W2_OFF + oo * HIDN + j] *
                           sm[ST_OFF + 400 + (j >> 1) * 8 + 2 * ob + (j & 1)];
                out[((size_t)(b0 + ob) * T_LEN + (t - 1)) * OUT_D + oo] = acc;
            }
        }
        __syncthreads();

        // ---- phase 2: upd1 (100 threads x 2 tasks) || helper stores x(t+1) ----
        if (isgate) {
#pragma unroll
            for (int kT = 0; kT < 2; kT++) {
                int b = ubt + 2 * kT;
                float iv = sm[ACT_OFF + uu * 4 + b];
                float fv = sm[ACT_OFF + (uu + 50) * 4 + b];
                float gv = sm[ACT_OFF + (uu + 100) * 4 + b];
                float ov = sm[ACT_OFF + (uu + 150) * 4 + b];
                c1s[kT] = fv * c1s[kT] + iv * gv;
                float h = ov * tanhap(c1s[kT]);
                sm[ST_OFF + up8 + 2 * b] = h;                 // h1 for cell2
                sm[IN1_OFF + 80 + up8 + 2 * b] = h;           // h1 for next cell1
            }
        } else if (ishelp && xl) {
            { int b = e0 / IN_D, k = e0 % IN_D;
              sm[IN1_OFF + (k >> 1) * 8 + 2 * b + (k & 1)] = xv0; }
            { int b = e1 / IN_D, k = e1 % IN_D;
              sm[IN1_OFF + (k >> 1) * 8 + 2 * b + (k & 1)] = xv1; }
            if (e2 < NB * IN_D) {
              int b = e2 / IN_D, k = e2 % IN_D;
              sm[IN1_OFF + (k >> 1) * 8 + 2 * b + (k & 1)] = xv2; }
        }
        __syncthreads();

        // ---- phase 3: gate2 from [h1 | h2] pairs ----
        if (isgate)
            cell_mv2<25>(wb0, wb1, bb0, bb1, 0.5f, 0.5f, 0.5f, k12, a12, c12,
                         sm + ST_OFF, sm + ACT_OFF, g, g + 100);
        __syncthreads();

        // ---- phase 4: upd2 (state = cz from prev step's cell3) ----
        if (isgate) {
#pragma unroll
            for (int kT = 0; kT < 2; kT++) {
                int b = ubt + 2 * kT;
                float iv = sm[ACT_OFF + uu * 4 + b];
                float fv = sm[ACT_OFF + (uu + 50) * 4 + b];
                float gv = sm[ACT_OFF + (uu + 100) * 4 + b];
                float ov = sm[ACT_OFF + (uu + 150) * 4 + b];
                float c2t = fv * czs[kT] + iv * gv;
                sm[ST_OFF + 200 + up8 + 2 * b] = ov * tanhap(c2t);   // h2
            }
        }
        __syncthreads();

        // ---- phase 5: gate3 from [h2 | h3]; 150 live rows, conflict-free ----
        if (is3)
            cell_mv2<25>(wc0, wc1, bc0, bc1, k3a, a3a, c3a, k3b, a3b, c3b,
                         sm + ST_OFF + 200, sm + ACT_OFF, r3a, r3b);
        __syncthreads();

        // ---- phase 6: upd3 (c_new = i*g; cz <- c_new) ----
        if (isgate) {
#pragma unroll
            for (int kT = 0; kT < 2; kT++) {
                int b = ubt + 2 * kT;
                float iv = sm[ACT_OFF + uu * 4 + b];
                float gv = sm[ACT_OFF + (uu + 100) * 4 + b];
                float ov = sm[ACT_OFF + (uu + 150) * 4 + b];
                czs[kT] = iv * gv;
                sm[ST_OFF + 400 + up8 + 2 * b] = ov * tanhap(czs[kT]);  // h3
            }
        }
        __syncthreads();
    }

    // tail: out-projection for the final step
    if (ishelp) {
        float acc = sm[B2_OFF + oo];
#pragma unroll
        for (int j = 0; j < HIDN; j++)
            acc += sm[W2_OFF + oo * HIDN + j] *
                   sm[ST_OFF + 400 + (j >> 1) * 8 + 2 * ob + (j & 1)];
        out[((size_t)(b0 + ob) * T_LEN + (T_LEN - 1)) * OUT_D + oo] = acc;
    }
}

extern "C" void kernel_launch(void* const* d_in, const int* in_sizes, int n_in,
                              void* d_out, int out_size)
{
    const float* x    = (const float*)d_in[0];
    const float* W1   = (const float*)d_in[1];
    const float* b1   = (const float*)d_in[2];
    const float* Wih1 = (const float*)d_in[3];
    const float* Whh1 = (const float*)d_in[4];
    const float* bih1 = (const float*)d_in[5];
    const float* bhh1 = (const float*)d_in[6];
    const float* Wih2 = (const float*)d_in[7];
    const float* Whh2 = (const float*)d_in[8];
    const float* bih2 = (const float*)d_in[9];
    const float* bhh2 = (const float*)d_in[10];
    const float* Wih3 = (const float*)d_in[11];
    const float* Whh3 = (const float*)d_in[12];
    const float* bih3 = (const float*)d_in[13];
    const float* bhh3 = (const float*)d_in[14];
    const float* W2   = (const float*)d_in[15];
    const float* b2   = (const float*)d_in[16];
    float* out = (float*)d_out;

    const int smem_bytes = SMEM_FLT * sizeof(float);  // 231,648
    cudaFuncSetAttribute(lstm_persist_kernel,
                         cudaFuncAttributeMaxDynamicSharedMemorySize, smem_bytes);

    lstm_persist_kernel<<<NCTA, NTH, smem_bytes>>>(
        x, W1, b1, Wih1, Whh1, bih1, bhh1,
        Wih2, Whh2, bih2, bhh2, Wih3, Whh3, bih3, bhh3,
        W2, b2, out);
}